// round 8
// baseline (speedup 1.0000x reference)
#include <cuda_runtime.h>

#define BATCH 4096
#define SEQ   64
#define HID   256
#define NHEAD 4
#define HDIM  64
#define KSTR  65   // padded row stride for K tile (kills 16-way bank conflict)

typedef unsigned long long ull;

// ---- packed f32x2 helpers (sm_100+ only; ptxas never auto-fuses these) ----
__device__ __forceinline__ ull pack2(float lo, float hi) {
    ull r; asm("mov.b64 %0, {%1, %2};" : "=l"(r) : "f"(lo), "f"(hi)); return r;
}
__device__ __forceinline__ float2 unpack2(ull v) {
    float2 f; asm("mov.b64 {%0, %1}, %2;" : "=f"(f.x), "=f"(f.y) : "l"(v)); return f;
}
__device__ __forceinline__ void fma2(ull& d, ull a, ull b) {
    asm("fma.rn.f32x2 %0, %1, %2, %0;" : "+l"(d) : "l"(a), "l"(b));
}

// Transposed weights [k][n] so GEMM loads are coalesced float4 across n.
__device__ float g_WT[4][HID * HID];

__global__ void prep_transpose(const float* __restrict__ Wq, const float* __restrict__ Wk,
                               const float* __restrict__ Wv, const float* __restrict__ Wo) {
    int idx = blockIdx.x * blockDim.x + threadIdx.x;   // 65536 threads total
    int k = idx >> 8, n = idx & 255;
    g_WT[0][idx] = Wq[n * HID + k];
    g_WT[1][idx] = Wk[n * HID + k];
    g_WT[2][idx] = Wv[n * HID + k];
    g_WT[3][idx] = Wo[n * HID + k];
}

// Shared memory layout (floats):
//   xs   : 64*256 = 16384
//   qh   : 64*64  =  4096
//   kh   : 64*65  =  4160   (padded stride)
//   vh   : 64*64  =  4096
//   sc   : 64*64  =  4096   (scores -> attn probs)
//   att  : 64*256 = 16384
//   asum : 64*64  =  4096   (attn mean-over-heads accumulator)
// total 53312 floats = 213248 B  (< 227 KB dynamic smem cap)
#define SMEM_FLOATS (SEQ*HID + SEQ*HDIM + SEQ*KSTR + SEQ*HDIM + SEQ*SEQ + SEQ*HID + SEQ*SEQ)

__global__ void __launch_bounds__(256, 1)
fused_kernel(const float* __restrict__ x,
             const float* __restrict__ bq, const float* __restrict__ bk,
             const float* __restrict__ bv, const float* __restrict__ bo,
             const float* __restrict__ ln_g, const float* __restrict__ ln_b,
             float* __restrict__ out, float* __restrict__ attn_out)
{
    extern __shared__ float smf[];
    float* xs   = smf;
    float* qh   = xs + SEQ * HID;
    float* kh   = qh + SEQ * HDIM;
    float* vh   = kh + SEQ * KSTR;
    float* sc   = vh + SEQ * HDIM;
    float* att  = sc + SEQ * SEQ;
    float* asum = att + SEQ * HID;
    float* ybuf = qh;            // reuse qh..sc region (16448 floats >= 16384) after heads

    const int b  = blockIdx.x;
    const int t  = threadIdx.x;
    const int tr = t >> 4, tc = t & 15;       // 16x16 thread grid
    const int r0 = tr * 4, c0 = tc * 4;       // 4x4 register tile per thread
    const int wrp = t >> 5, ln = t & 31;

    // ---- stage x rows 8w..8w+7 (warp-local), zero own asum rows ----
    {
        const float4* src = (const float4*)(x + (size_t)b * SEQ * HID);
        float4* dst = (float4*)xs;                    // 64 float4 per row
        #pragma unroll
        for (int i = 0; i < 16; i++) {
            int idx = wrp * 512 + ln + 32 * i;        // rows 8w..8w+7
            dst[idx] = src[idx];
        }
        float4 z = make_float4(0.f, 0.f, 0.f, 0.f);
        float4* az = (float4*)asum;                   // 16 float4 per row
        #pragma unroll
        for (int i = 0; i < 4; i++) az[wrp * 128 + ln + 32 * i] = z;
    }
    // no barrier: QKV projection reads xs rows r0..r0+3 (own warp only)

    for (int h = 0; h < NHEAD; h++) {
        // ---- fused Q/K/V projection for this head: [64,256]@[256,64] x3 ----
        // Weight LDGs (L2-latency) are double-buffered one 4-k chunk ahead;
        // xs operands are LDS (cheap) and loaded in-chunk.
        ull aq[4][2], ak[4][2], av[4][2];
        #pragma unroll
        for (int i = 0; i < 4; i++) {
            aq[i][0] = aq[i][1] = 0ull;
            ak[i][0] = ak[i][1] = 0ull;
            av[i][0] = av[i][1] = 0ull;
        }
        const float* wq = g_WT[0] + h * HDIM + c0;
        const float* wk = g_WT[1] + h * HDIM + c0;
        const float* wv = g_WT[2] + h * HDIM + c0;

        auto qkv_load = [&](float4 (&Q)[4], float4 (&K)[4], float4 (&V)[4], int k) {
            #pragma unroll
            for (int kk = 0; kk < 4; kk++) {
                Q[kk] = *(const float4*)(wq + (k + kk) * HID);
                K[kk] = *(const float4*)(wk + (k + kk) * HID);
                V[kk] = *(const float4*)(wv + (k + kk) * HID);
            }
        };
        auto qkv_comp = [&](const float4 (&Q)[4], const float4 (&K)[4],
                            const float4 (&V)[4], int k) {
            float4 xv4[4];
            #pragma unroll
            for (int i = 0; i < 4; i++) xv4[i] = *(const float4*)&xs[(r0 + i) * HID + k];
            float xv[4][4];
            #pragma unroll
            for (int i = 0; i < 4; i++) {
                xv[i][0] = xv4[i].x; xv[i][1] = xv4[i].y;
                xv[i][2] = xv4[i].z; xv[i][3] = xv4[i].w;
            }
            #pragma unroll
            for (int kk = 0; kk < 4; kk++) {
                ull q01 = pack2(Q[kk].x, Q[kk].y), q23 = pack2(Q[kk].z, Q[kk].w);
                ull k01 = pack2(K[kk].x, K[kk].y), k23 = pack2(K[kk].z, K[kk].w);
                ull v01 = pack2(V[kk].x, V[kk].y), v23 = pack2(V[kk].z, V[kk].w);
                #pragma unroll
                for (int i = 0; i < 4; i++) {
                    ull xx = pack2(xv[i][kk], xv[i][kk]);
                    fma2(aq[i][0], xx, q01); fma2(aq[i][1], xx, q23);
                    fma2(ak[i][0], xx, k01); fma2(ak[i][1], xx, k23);
                    fma2(av[i][0], xx, v01); fma2(av[i][1], xx, v23);
                }
            }
        };

        {
            float4 qA[4], kA[4], vA[4], qB[4], kB[4], vB[4];
            qkv_load(qA, kA, vA, 0);                      // preload chunk 0
            for (int k = 0; k < HID; k += 8) {            // rolled: 32 iters
                qkv_load(qB, kB, vB, k + 4);              // prefetch chunk k+4
                qkv_comp(qA, kA, vA, k);                  // compute chunk k
                if (k + 8 < HID) qkv_load(qA, kA, vA, k + 8);  // prefetch k+8
                qkv_comp(qB, kB, vB, k + 4);              // compute chunk k+4
            }
        }
        {
            float4 bq4 = *(const float4*)(bq + h * HDIM + c0);
            float4 bk4 = *(const float4*)(bk + h * HDIM + c0);
            float4 bv4 = *(const float4*)(bv + h * HDIM + c0);
            #pragma unroll
            for (int i = 0; i < 4; i++) {
                float2 a = unpack2(aq[i][0]), c = unpack2(aq[i][1]);
                *(float4*)&qh[(r0 + i) * HDIM + c0] =
                    make_float4(a.x + bq4.x, a.y + bq4.y, c.x + bq4.z, c.y + bq4.w);
                a = unpack2(ak[i][0]); c = unpack2(ak[i][1]);
                kh[(r0 + i) * KSTR + c0 + 0] = a.x + bk4.x;
                kh[(r0 + i) * KSTR + c0 + 1] = a.y + bk4.y;
                kh[(r0 + i) * KSTR + c0 + 2] = c.x + bk4.z;
                kh[(r0 + i) * KSTR + c0 + 3] = c.y + bk4.w;
                a = unpack2(av[i][0]); c = unpack2(av[i][1]);
                *(float4*)&vh[(r0 + i) * HDIM + c0] =
                    make_float4(a.x + bv4.x, a.y + bv4.y, c.x + bv4.z, c.y + bv4.w);
            }
        }
        __syncthreads();   // kh/vh are read cross-warp below — real barrier

        // ---- scores = Q @ K^T * (1/sqrt(64)), packed f32x2 over j ----
        {
            ull s01[4], s23[4];
            #pragma unroll
            for (int i = 0; i < 4; i++) { s01[i] = 0ull; s23[i] = 0ull; }
            for (int d = 0; d < HDIM; d += 4) {
                float qv[4][4];
                #pragma unroll
                for (int i = 0; i < 4; i++) {
                    float4 q4 = *(const float4*)&qh[(r0 + i) * HDIM + d];
                    qv[i][0] = q4.x; qv[i][1] = q4.y; qv[i][2] = q4.z; qv[i][3] = q4.w;
                }
                #pragma unroll
                for (int dd = 0; dd < 4; dd++) {
                    float k0 = kh[(c0 + 0) * KSTR + d + dd], k1 = kh[(c0 + 1) * KSTR + d + dd];
                    float k2 = kh[(c0 + 2) * KSTR + d + dd], k3 = kh[(c0 + 3) * KSTR + d + dd];
                    ull k01 = pack2(k0, k1), k23 = pack2(k2, k3);
                    #pragma unroll
                    for (int i = 0; i < 4; i++) {
                        ull qq = pack2(qv[i][dd], qv[i][dd]);
                        fma2(s01[i], qq, k01);
                        fma2(s23[i], qq, k23);
                    }
                }
            }
            #pragma unroll
            for (int i = 0; i < 4; i++) {
                float2 a = unpack2(s01[i]), c = unpack2(s23[i]);
                *(float4*)&sc[(r0 + i) * SEQ + c0] =
                    make_float4(a.x * 0.125f, a.y * 0.125f, c.x * 0.125f, c.y * 0.125f);
            }
        }
        __syncwarp();      // sc rows 8w..8w+7 produced & consumed within warp w

        // ---- row softmax (warp w owns rows 8w..8w+7) + attn-avg accumulate ----
        #pragma unroll
        for (int j = 0; j < 8; j++) {
            int q = wrp * 8 + j;
            float s0 = sc[q * SEQ + ln], s1 = sc[q * SEQ + ln + 32];
            float m = fmaxf(s0, s1);
            #pragma unroll
            for (int o = 16; o > 0; o >>= 1) m = fmaxf(m, __shfl_xor_sync(0xffffffffu, m, o));
            float e0 = __expf(s0 - m), e1 = __expf(s1 - m);
            float sum = e0 + e1;
            #pragma unroll
            for (int o = 16; o > 0; o >>= 1) sum += __shfl_xor_sync(0xffffffffu, sum, o);
            float inv = 1.0f / sum;
            float a0 = e0 * inv, a1 = e1 * inv;
            sc[q * SEQ + ln]      = a0;
            sc[q * SEQ + ln + 32] = a1;
            asum[q * SEQ + ln]      += 0.25f * a0;
            asum[q * SEQ + ln + 32] += 0.25f * a1;
        }
        __syncwarp();      // sc/asum still warp-local

        // ---- attended[:, h*64:(h+1)*64] = attn @ V, packed f32x2 over j ----
        {
            ull a01[4], a23[4];
            #pragma unroll
            for (int i = 0; i < 4; i++) { a01[i] = 0ull; a23[i] = 0ull; }
            for (int kk = 0; kk < SEQ; kk += 4) {
                float pv[4][4];
                float4 vv[4];
                #pragma unroll
                for (int k2 = 0; k2 < 4; k2++)
                    vv[k2] = *(const float4*)&vh[(kk + k2) * HDIM + c0];
                #pragma unroll
                for (int i = 0; i < 4; i++) {
                    float4 p4 = *(const float4*)&sc[(r0 + i) * SEQ + kk];
                    pv[i][0] = p4.x; pv[i][1] = p4.y; pv[i][2] = p4.z; pv[i][3] = p4.w;
                }
                #pragma unroll
                for (int k2 = 0; k2 < 4; k2++) {
                    ull v01 = pack2(vv[k2].x, vv[k2].y), v23 = pack2(vv[k2].z, vv[k2].w);
                    #pragma unroll
                    for (int i = 0; i < 4; i++) {
                        ull pp = pack2(pv[i][k2], pv[i][k2]);
                        fma2(a01[i], pp, v01);
                        fma2(a23[i], pp, v23);
                    }
                }
            }
            #pragma unroll
            for (int i = 0; i < 4; i++) {
                float2 a = unpack2(a01[i]), c = unpack2(a23[i]);
                *(float4*)&att[(r0 + i) * HID + h * HDIM + c0] =
                    make_float4(a.x, a.y, c.x, c.y);
            }
        }
        __syncthreads();   // next head overwrites kh/vh which were read cross-warp
    }

    // ---- output projection + residual: y = x + att @ Wo^T + bo ----
    // Weight LDGs double-buffered one chunk ahead; att is LDS, loaded in-chunk.
    const float* wo = g_WT[3];
    for (int cg = 0; cg < 4; cg++) {
        int cc = cg * 64 + c0;
        ull ac[4][2];
        #pragma unroll
        for (int i = 0; i < 4; i++) ac[i][0] = ac[i][1] = 0ull;

        auto wo_load = [&](float4 (&W)[4], int k) {
            #pragma unroll
            for (int kk = 0; kk < 4; kk++)
                W[kk] = *(const float4*)(wo + (k + kk) * HID + cc);
        };
        auto wo_comp = [&](const float4 (&W)[4], int k) {
            float4 a4[4];
            #pragma unroll
            for (int i = 0; i < 4; i++)
                a4[i] = *(const float4*)&att[(r0 + i) * HID + k];
            float av4[4][4];
            #pragma unroll
            for (int i = 0; i < 4; i++) {
                av4[i][0] = a4[i].x; av4[i][1] = a4[i].y;
                av4[i][2] = a4[i].z; av4[i][3] = a4[i].w;
            }
            #pragma unroll
            for (int kk = 0; kk < 4; kk++) {
                ull w01 = pack2(W[kk].x, W[kk].y), w23 = pack2(W[kk].z, W[kk].w);
                #pragma unroll
                for (int i = 0; i < 4; i++) {
                    ull aa = pack2(av4[i][kk], av4[i][kk]);
                    fma2(ac[i][0], aa, w01);
                    fma2(ac[i][1], aa, w23);
                }
            }
        };

        {
            float4 wA[4], wB[4];
            wo_load(wA, 0);
            for (int k = 0; k < HID; k += 8) {
                wo_load(wB, k + 4);
                wo_comp(wA, k);
                if (k + 8 < HID) wo_load(wA, k + 8);
                wo_comp(wB, k + 4);
            }
        }
        float4 bo4 = *(const float4*)(bo + cc);
        #pragma unroll
        for (int i = 0; i < 4; i++) {
            float2 a = unpack2(ac[i][0]), c = unpack2(ac[i][1]);
            float4 xr = *(const float4*)&xs[(r0 + i) * HID + cc];
            *(float4*)&ybuf[(r0 + i) * HID + cc] =
                make_float4(a.x + bo4.x + xr.x, a.y + bo4.y + xr.y,
                            c.x + bo4.z + xr.z, c.y + bo4.w + xr.w);
        }
    }
    __syncwarp();          // ybuf rows 8w..8w+7 written by own warp, read below

    // ---- LayerNorm per row + store output (warp-local rows, vectorized) ----
    {
        float* ob = out + (size_t)b * SEQ * HID;
        const int cb = 8 * ln;
        const float4 g0 = *(const float4*)(ln_g + cb);
        const float4 g1 = *(const float4*)(ln_g + cb + 4);
        const float4 be0 = *(const float4*)(ln_b + cb);
        const float4 be1 = *(const float4*)(ln_b + cb + 4);
        #pragma unroll
        for (int j = 0; j < 8; j++) {
            int r = wrp * 8 + j;
            float4 va = *(const float4*)&ybuf[r * HID + cb];
            float4 vb = *(const float4*)&ybuf[r * HID + cb + 4];
            float s  = (va.x + va.y) + (va.z + va.w) + (vb.x + vb.y) + (vb.z + vb.w);
            float ss = va.x * va.x + va.y * va.y + va.z * va.z + va.w * va.w
                     + vb.x * vb.x + vb.y * vb.y + vb.z * vb.z + vb.w * vb.w;
            #pragma unroll
            for (int o = 16; o > 0; o >>= 1) {
                s  += __shfl_xor_sync(0xffffffffu, s, o);
                ss += __shfl_xor_sync(0xffffffffu, ss, o);
            }
            float mu  = s * (1.0f / HID);
            float var = ss * (1.0f / HID) - mu * mu;
            float rstd = rsqrtf(var + 1e-5f);
            float4 o0, o1;
            o0.x = (va.x - mu) * rstd * g0.x + be0.x;
            o0.y = (va.y - mu) * rstd * g0.y + be0.y;
            o0.z = (va.z - mu) * rstd * g0.z + be0.z;
            o0.w = (va.w - mu) * rstd * g0.w + be0.w;
            o1.x = (vb.x - mu) * rstd * g1.x + be1.x;
            o1.y = (vb.y - mu) * rstd * g1.y + be1.y;
            o1.z = (vb.z - mu) * rstd * g1.z + be1.z;
            o1.w = (vb.w - mu) * rstd * g1.w + be1.w;
            *(float4*)&ob[r * HID + cb]     = o0;
            *(float4*)&ob[r * HID + cb + 4] = o1;
        }
    }

    // ---- store attn average rows 8w..8w+7 (warp-local, no barrier) ----
    {
        float4* dst = (float4*)(attn_out + (size_t)b * SEQ * SEQ);
        const float4* src = (const float4*)asum;
        #pragma unroll
        for (int i = 0; i < 4; i++) {
            int idx = wrp * 128 + ln + 32 * i;
            dst[idx] = src[idx];
        }
    }
}

extern "C" void kernel_launch(void* const* d_in, const int* in_sizes, int n_in,
                              void* d_out, int out_size) {
    const float* x    = (const float*)d_in[0];
    const float* Wq   = (const float*)d_in[1];
    const float* bq   = (const float*)d_in[2];
    const float* Wk   = (const float*)d_in[3];
    const float* bk   = (const float*)d_in[4];
    const float* Wv   = (const float*)d_in[5];
    const float* bv   = (const float*)d_in[6];
    const float* Wo   = (const float*)d_in[7];
    const float* bo   = (const float*)d_in[8];
    const float* g    = (const float*)d_in[9];
    const float* bt   = (const float*)d_in[10];

    float* out      = (float*)d_out;
    float* attn_out = out + (size_t)BATCH * SEQ * HID;   // [B,A,H] then [B,A,A]

    const int smem_bytes = SMEM_FLOATS * (int)sizeof(float);
    cudaFuncSetAttribute(fused_kernel, cudaFuncAttributeMaxDynamicSharedMemorySize, smem_bytes);

    prep_transpose<<<256, 256>>>(Wq, Wk, Wv, Wo);
    fused_kernel<<<BATCH, 256, smem_bytes>>>(x, bq, bk, bv, bo, g, bt, out, attn_out);
}